// round 14
// baseline (speedup 1.0000x reference)
#include <cuda_runtime.h>
#include <cuda_fp16.h>
#include <math.h>
#include <stdint.h>

// Problem dims (fixed by the dataset)
#define B_   2
#define T_   2048
#define C_   1024
#define H_   16
#define HD_  64
#define C3_  (3*C_)
#define M_   (B_*T_)          // 4096 rows

// ---------------- scratch (no cudaMalloc allowed) ----------------
__device__ __half g_qkv[(size_t)M_ * C3_];      // fp16 qkv
__device__ __half g_x  [(size_t)M_ * C_];       // fp16 x
__device__ __half g_y  [(size_t)M_ * C_];       // fp16 y
__device__ __half g_wqkvT[(size_t)C3_ * C_];    // [N=3C][K=C] fp16
__device__ __half g_woutT[(size_t)C_ * C_];     // [N=C][K=C] fp16
__device__ int g_ctr[2];                        // persistent-GEMM tile counters

// ---------------- helpers ----------------
__device__ __forceinline__ uint32_t smem_u32(const void* p) {
    return (uint32_t)__cvta_generic_to_shared(p);
}
__device__ __forceinline__ void cp_async16(void* s, const void* g) {
    asm volatile("cp.async.cg.shared.global [%0], [%1], 16;\n"
                 :: "r"(smem_u32(s)), "l"(g));
}
__device__ __forceinline__ void cp_commit() {
    asm volatile("cp.async.commit_group;\n" ::);
}
__device__ __forceinline__ void cp_wait0() {
    asm volatile("cp.async.wait_group 0;\n" ::);
}
__device__ __forceinline__ void mma_f16(float* d, const uint32_t* a, const uint32_t* b) {
    asm volatile(
        "mma.sync.aligned.m16n8k16.row.col.f32.f16.f16.f32 "
        "{%0,%1,%2,%3}, {%4,%5,%6,%7}, {%8,%9}, {%0,%1,%2,%3};\n"
        : "+f"(d[0]), "+f"(d[1]), "+f"(d[2]), "+f"(d[3])
        : "r"(a[0]), "r"(a[1]), "r"(a[2]), "r"(a[3]),
          "r"(b[0]), "r"(b[1]));
}
__device__ __forceinline__ void ldsm_x4(uint32_t* r, uint32_t addr) {
    asm volatile("ldmatrix.sync.aligned.m8n8.x4.shared.b16 {%0,%1,%2,%3}, [%4];"
                 : "=r"(r[0]), "=r"(r[1]), "=r"(r[2]), "=r"(r[3])
                 : "r"(addr));
}
__device__ __forceinline__ void ldsm_x4_trans(uint32_t* r, uint32_t addr) {
    asm volatile("ldmatrix.sync.aligned.m8n8.x4.trans.shared.b16 {%0,%1,%2,%3}, [%4];"
                 : "=r"(r[0]), "=r"(r[1]), "=r"(r[2]), "=r"(r[3])
                 : "r"(addr));
}
// pack two floats into fp16x2 (first arg -> low half)
__device__ __forceinline__ uint32_t pack_f16x2(float lo, float hi) {
    uint32_t r;
    asm("cvt.rn.f16x2.f32 %0, %1, %2;" : "=r"(r) : "f"(hi), "f"(lo));
    return r;
}

// ---------------- fused prep kernel (one launch) ----------------
#define PREP_GRID (256 + 3072 + 1024)

__global__ __launch_bounds__(256) void prep_kernel(
    const float* __restrict__ x, __half* __restrict__ xh,
    const float* __restrict__ wqkv, __half* __restrict__ wq,
    const float* __restrict__ wout, __half* __restrict__ wo)
{
    const int bid = blockIdx.x;
    const int t   = threadIdx.x;
    if (bid == 0 && t == 0) { g_ctr[0] = 0; g_ctr[1] = 0; }

    if (bid < 256) {
        const int n = M_ * C_;
        for (int i = bid * 256 + t; i < n; i += 256 * 256)
            xh[i] = __float2half_rn(x[i]);
        return;
    }

    __shared__ float ts[32][33];
    const int tx = t & 31;
    const int ty = t >> 5;
    const int K  = C_;

    const float* src; __half* dst; int N, tileid, ncols;
    if (bid < 256 + 3072) {
        tileid = bid - 256;  src = wqkv; dst = wq; N = C3_; ncols = 96;
    } else {
        tileid = bid - 3328; src = wout; dst = wo; N = C_;  ncols = 32;
    }
    const int n0 = (tileid % ncols) * 32;
    const int k0 = (tileid / ncols) * 32;
#pragma unroll
    for (int i = 0; i < 4; i++) {
        int k = k0 + ty + i * 8;
        ts[ty + i * 8][tx] = src[(size_t)k * N + n0 + tx];
    }
    __syncthreads();
#pragma unroll
    for (int i = 0; i < 4; i++) {
        int n = n0 + ty + i * 8;
        dst[(size_t)n * K + k0 + tx] = __float2half_rn(ts[tx][ty + i * 8]);
    }
}

// shared GEMM geometry
#define GBM 128
#define GBN 128
#define GBK 64                         // K depth per stage (fewer barriers)
#define TSTRIDE 36                     // uint32 words per SMEM tile row (144 B)
#define TILE_WORDS (128 * TSTRIDE)     // 4608 words = 18 KB per operand tile
#define GEMM_GRID 304                  // 2 CTAs x 152 SMs

// ================= fp16 persistent GEMM (BK=64) =================
// D = A[M,K] @ B^T + bias; A fp16 [M][K], B fp16 [N][K], fp32 accumulate.
// Output: fp16 (Ch != nullptr) or fp32 (Cout).
// 128 threads = 4 warps (2x2), warp tile 64x64. SMEM 72 KB/CTA (2 buf).
__global__ __launch_bounds__(128, 2) void gemm_f16_kernel(
    const __half* __restrict__ A, const __half* __restrict__ Bw,
    const float* __restrict__ bias,
    float* __restrict__ Cout, __half* __restrict__ Ch,
    int M, int N, int K, int ctr_slot)
{
    extern __shared__ uint32_t sm[];
    __shared__ int s_next;
    uint32_t* tiles[2][2];   // 0=A 1=B
#pragma unroll
    for (int b = 0; b < 2; b++)
#pragma unroll
        for (int t = 0; t < 2; t++)
            tiles[b][t] = sm + (b * 2 + t) * TILE_WORDS;

    const int tid  = threadIdx.x;
    const int wid  = tid >> 5;
    const int lane = tid & 31;
    const int g    = lane >> 2;
    const int q    = lane & 3;
    const int wm   = (wid & 1) * 64;
    const int wn   = (wid >> 1) * 64;

    const int grp = lane >> 3;
    const int rl  = lane & 7;
    uint32_t aRel[4];
#pragma unroll
    for (int mi = 0; mi < 4; mi++)
        aRel[mi] = (uint32_t)((wm + mi * 16 + (grp & 1) * 8 + rl) * 144
                              + (grp >> 1) * 16);
    uint32_t bRel[4];
#pragma unroll
    for (int ni2 = 0; ni2 < 4; ni2++)
        bRel[ni2] = (uint32_t)((wn + ni2 * 16 + (grp >> 1) * 8 + rl) * 144
                               + (grp & 1) * 16);

    const int ncol    = N / GBN;
    const int n_tiles = (M / GBM) * ncol;
    int ti = blockIdx.x;

    while (ti < n_tiles) {
        const int row0 = (ti / ncol) * GBM;
        const int col0 = (ti % ncol) * GBN;

        float acc[4][8][4];
#pragma unroll
        for (int mi = 0; mi < 4; mi++)
#pragma unroll
            for (int ni = 0; ni < 8; ni++)
#pragma unroll
                for (int r = 0; r < 4; r++) acc[mi][ni][r] = 0.f;

        const __half* srcs[2] = {A, Bw};
        // tile: 128 rows x 64 fp16 = 8 x 16B chunks per row
        auto load_tile = [&](int kt, int buf) {
            const int k0 = kt * GBK;
#pragma unroll
            for (int t = 0; t < 2; t++) {
                const __half* base = srcs[t] +
                    (size_t)((t < 1) ? row0 : col0) * K + k0;
#pragma unroll
                for (int it = 0; it < 8; it++) {
                    int idx = tid + it * 128;       // 0..1023
                    int r   = idx >> 3;             // row 0..127
                    int ch  = idx & 7;              // 16B chunk
                    cp_async16(&tiles[buf][t][r * TSTRIDE + ch * 4],
                               base + (size_t)r * K + ch * 8);
                }
            }
            cp_commit();
        };

        load_tile(0, 0);
        cp_wait0();
        __syncthreads();

        const int KT = K / GBK;   // 16
        for (int kt = 0; kt < KT; kt++) {
            const int buf = kt & 1;
            if (kt + 1 < KT) load_tile(kt + 1, buf ^ 1);

            const uint32_t baseA = smem_u32(tiles[buf][0]);
            const uint32_t baseB = smem_u32(tiles[buf][1]);

#pragma unroll
            for (int ks = 0; ks < 4; ks++) {        // 4 k16 steps per BK=64
                const uint32_t ko = (uint32_t)ks * 32;
                uint32_t af[4][4], bf[8][2];
#pragma unroll
                for (int mi = 0; mi < 4; mi++)
                    ldsm_x4(af[mi], baseA + aRel[mi] + ko);
#pragma unroll
                for (int ni2 = 0; ni2 < 4; ni2++) {
                    uint32_t t4[4];
                    ldsm_x4(t4, baseB + bRel[ni2] + ko);
                    bf[2*ni2][0] = t4[0]; bf[2*ni2][1] = t4[1];
                    bf[2*ni2+1][0] = t4[2]; bf[2*ni2+1][1] = t4[3];
                }
#pragma unroll
                for (int mi = 0; mi < 4; mi++)
#pragma unroll
                    for (int ni = 0; ni < 8; ni++)
                        mma_f16(acc[mi][ni], af[mi], bf[ni]);
            }

            if (kt + 1 < KT) cp_wait0();
            __syncthreads();
        }

        // ---- epilogue ----
#pragma unroll
        for (int mi = 0; mi < 4; mi++) {
#pragma unroll
            for (int ni = 0; ni < 8; ni++) {
                int r = row0 + wm + mi * 16 + g;
                int c = col0 + wn + ni * 8 + 2 * q;
                float b0 = bias[c], b1 = bias[c + 1];
                float v00 = acc[mi][ni][0] + b0, v01 = acc[mi][ni][1] + b1;
                float v10 = acc[mi][ni][2] + b0, v11 = acc[mi][ni][3] + b1;
                if (Ch) {
                    *(uint32_t*)(Ch + (size_t)r * N + c)       = pack_f16x2(v00, v01);
                    *(uint32_t*)(Ch + (size_t)(r + 8) * N + c) = pack_f16x2(v10, v11);
                } else {
                    *(float2*)(Cout + (size_t)r * N + c)       = make_float2(v00, v01);
                    *(float2*)(Cout + (size_t)(r + 8) * N + c) = make_float2(v10, v11);
                }
            }
        }

        if (tid == 0) s_next = (int)gridDim.x + atomicAdd(&g_ctr[ctr_slot], 1);
        __syncthreads();
        ti = s_next;
        __syncthreads();
    }
}

// ================= MMA flash attention (fp16, fp32 softmax) ========
// (unchanged from R13 — controlled experiment)
#define ATT_SMEM (9216 * 4)

__global__ __launch_bounds__(256, 2) void attn_mma_kernel(
    const __half* __restrict__ qkv, __half* __restrict__ y)
{
    extern __shared__ uint32_t smd[];
    uint32_t* smB[2] = {smd, smd + 4608};

    const int tid  = threadIdx.x;
    const int w    = tid >> 5;
    const int lane = tid & 31;
    const int g    = lane >> 2;
    const int q    = lane & 3;
    const int grp  = lane >> 3;
    const int rl   = lane & 7;
    const int bh   = blockIdx.x;
    const int b    = bh >> 4;
    const int h    = bh & 15;
    const int qt   = (gridDim.y - 1) - blockIdx.y;   // heavy blocks first
    const int qb   = qt * 128;

    // ---- stage Q, extract fragments ----
#pragma unroll
    for (int it = 0; it < 4; it++) {
        int idx = tid + it * 256;            // 0..1023
        int row = idx >> 3;
        int ch  = idx & 7;
        const __half* src = qkv
            + (size_t)(b * T_ + qb + row) * C3_ + h * HD_ + ch * 8;
        cp_async16(&smd[row * 36 + ch * 4], src);
    }
    cp_commit();
    cp_wait0();
    __syncthreads();

    uint32_t qf[4][4];
    {
        uint32_t qa = smem_u32(&smd[0])
            + (uint32_t)((w * 16 + (grp & 1) * 8 + rl) * 144 + (grp >> 1) * 16);
#pragma unroll
        for (int ks = 0; ks < 4; ks++)
            ldsm_x4(qf[ks], qa + ks * 32);
    }
    __syncthreads();   // SMEM free for K/V

    const __half* kv_src[2] = {qkv + C_, qkv + 2 * C_};
    auto load_tile = [&](int kt, int bufi) {
        const int k0 = kt * 64;
#pragma unroll
        for (int it = 0; it < 4; it++) {
            int idx = tid + it * 256;        // 0..1023
            int arr = idx >> 9;              // 0=K,1=V
            int rem = idx & 511;
            int row = rem >> 3;
            int ch  = rem & 7;
            const __half* src = kv_src[arr]
                + (size_t)(b * T_ + k0 + row) * C3_ + h * HD_ + ch * 8;
            cp_async16(&smB[bufi][arr * 2304 + row * 36 + ch * 4], src);
        }
        cp_commit();
    };

    float o[8][4];
#pragma unroll
    for (int nj = 0; nj < 8; nj++)
#pragma unroll
        for (int c = 0; c < 4; c++) o[nj][c] = 0.f;
    float m0 = -INFINITY, m1 = -INFINITY;
    float l0 = 0.f, l1 = 0.f;

    const int qrow0 = qb + w * 16 + g;
    const int qrow1 = qrow0 + 8;
    const int qmax_w = qb + w * 16 + 15;
    const int kt_max = (qb + 127) >> 6;

    load_tile(0, 0);
    cp_wait0();
    __syncthreads();

    for (int kt = 0; kt <= kt_max; kt++) {
        const int bufi = kt & 1;
        const int k0 = kt * 64;
        if (kt + 1 <= kt_max) load_tile(kt + 1, bufi ^ 1);

        if (k0 <= qmax_w) {
            const uint32_t sb = smem_u32(&smB[bufi][0]);

            // ---- S = Q K^T ----
            float s[8][4];
#pragma unroll
            for (int ni2 = 0; ni2 < 4; ni2++) {
#pragma unroll
                for (int c = 0; c < 4; c++) {
                    s[2*ni2][c] = 0.f; s[2*ni2+1][c] = 0.f;
                }
                const uint32_t ka = sb
                    + (uint32_t)((ni2 * 16 + (grp >> 1) * 8 + rl) * 144
                                 + (grp & 1) * 16);
#pragma unroll
                for (int ks = 0; ks < 4; ks++) {
                    uint32_t k4[4];
                    ldsm_x4(k4, ka + ks * 32);
                    mma_f16(s[2*ni2],   qf[ks], k4);
                    mma_f16(s[2*ni2+1], qf[ks], k4 + 2);
                }
            }
#pragma unroll
            for (int ni = 0; ni < 8; ni++)
#pragma unroll
                for (int c = 0; c < 4; c++) s[ni][c] *= 0.125f;

            // ---- causal mask ----
            if (k0 + 63 > qb + w * 16) {
#pragma unroll
                for (int ni = 0; ni < 8; ni++) {
                    int key = k0 + 8 * ni + 2 * q;
                    s[ni][0] = (key     <= qrow0) ? s[ni][0] : -INFINITY;
                    s[ni][1] = (key + 1 <= qrow0) ? s[ni][1] : -INFINITY;
                    s[ni][2] = (key     <= qrow1) ? s[ni][2] : -INFINITY;
                    s[ni][3] = (key + 1 <= qrow1) ? s[ni][3] : -INFINITY;
                }
            }

            // ---- online softmax ----
            float mx0 = s[0][0], mx1 = s[0][2];
#pragma unroll
            for (int ni = 0; ni < 8; ni++) {
                mx0 = fmaxf(mx0, fmaxf(s[ni][0], s[ni][1]));
                mx1 = fmaxf(mx1, fmaxf(s[ni][2], s[ni][3]));
            }
            mx0 = fmaxf(mx0, __shfl_xor_sync(0xffffffff, mx0, 1));
            mx0 = fmaxf(mx0, __shfl_xor_sync(0xffffffff, mx0, 2));
            mx1 = fmaxf(mx1, __shfl_xor_sync(0xffffffff, mx1, 1));
            mx1 = fmaxf(mx1, __shfl_xor_sync(0xffffffff, mx1, 2));

            float mn0 = fmaxf(m0, mx0), mn1 = fmaxf(m1, mx1);
            float al0 = __expf(m0 - mn0), al1 = __expf(m1 - mn1);
            m0 = mn0; m1 = mn1;
            l0 *= al0; l1 *= al1;
#pragma unroll
            for (int nj = 0; nj < 8; nj++) {
                o[nj][0] *= al0; o[nj][1] *= al0;
                o[nj][2] *= al1; o[nj][3] *= al1;
            }

            // ---- per k16 step: pack P, O += P V ----
#pragma unroll
            for (int ks = 0; ks < 4; ks++) {
                uint32_t af[4];
#pragma unroll
                for (int half = 0; half < 2; half++) {
                    const int ni = 2 * ks + half;
                    float p0 = __expf(s[ni][0] - mn0);
                    float p1 = __expf(s[ni][1] - mn0);
                    float p2 = __expf(s[ni][2] - mn1);
                    float p3 = __expf(s[ni][3] - mn1);
                    l0 += p0 + p1;
                    l1 += p2 + p3;
                    af[2*half]     = pack_f16x2(p0, p1);
                    af[2*half + 1] = pack_f16x2(p2, p3);
                }
                const uint32_t va = sb + 2304 * 4
                    + (uint32_t)((ks * 16 + (grp & 1) * 8 + rl) * 144
                                 + (grp >> 1) * 16);
#pragma unroll
                for (int nj2 = 0; nj2 < 4; nj2++) {
                    uint32_t v4[4];
                    ldsm_x4_trans(v4, va + nj2 * 32);
                    mma_f16(o[2*nj2],   af, v4);
                    mma_f16(o[2*nj2+1], af, v4 + 2);
                }
            }
        }

        cp_wait0();
        __syncthreads();
    }

    // ---- epilogue ----
    l0 += __shfl_xor_sync(0xffffffff, l0, 1);
    l0 += __shfl_xor_sync(0xffffffff, l0, 2);
    l1 += __shfl_xor_sync(0xffffffff, l1, 1);
    l1 += __shfl_xor_sync(0xffffffff, l1, 2);
    const float inv0 = 1.f / l0;
    const float inv1 = 1.f / l1;

    __half* y0 = y + (size_t)(b * T_ + qrow0) * C_ + h * HD_;
    __half* y1 = y + (size_t)(b * T_ + qrow1) * C_ + h * HD_;
#pragma unroll
    for (int nj = 0; nj < 8; nj++) {
        int c = 8 * nj + 2 * q;
        *(uint32_t*)(y0 + c) = pack_f16x2(o[nj][0] * inv0, o[nj][1] * inv0);
        *(uint32_t*)(y1 + c) = pack_f16x2(o[nj][2] * inv1, o[nj][3] * inv1);
    }
}

// ---------------- launch ----------------
extern "C" void kernel_launch(void* const* d_in, const int* in_sizes, int n_in,
                              void* d_out, int out_size)
{
    const float* x     = (const float*)d_in[0];
    const float* w_qkv = (const float*)d_in[1];
    const float* b_qkv = (const float*)d_in[2];
    const float* w_out = (const float*)d_in[3];
    const float* b_out = (const float*)d_in[4];
    float* out = (float*)d_out;

    __half *qkvp, *xh, *yh, *wq, *wo;
    cudaGetSymbolAddress((void**)&qkvp, g_qkv);
    cudaGetSymbolAddress((void**)&xh, g_x);
    cudaGetSymbolAddress((void**)&yh, g_y);
    cudaGetSymbolAddress((void**)&wq, g_wqkvT);
    cudaGetSymbolAddress((void**)&wo, g_woutT);

    static bool attr_set = false;
    if (!attr_set) {
        cudaFuncSetAttribute(gemm_f16_kernel,
                             cudaFuncAttributeMaxDynamicSharedMemorySize,
                             4 * TILE_WORDS * 4);
        cudaFuncSetAttribute(attn_mma_kernel,
                             cudaFuncAttributeMaxDynamicSharedMemorySize,
                             ATT_SMEM);
        attr_set = true;
    }
    const int gemm_smem = 4 * TILE_WORDS * 4;   // 73728 B

    // 0) fused prep: convert x, transpose+convert both weights
    prep_kernel<<<PREP_GRID, 256>>>(x, xh, w_qkv, wq, w_out, wo);

    // 1) qkv = x @ w_qkv + b_qkv  -> fp16
    gemm_f16_kernel<<<GEMM_GRID, 128, gemm_smem>>>(
        xh, wq, b_qkv, nullptr, qkvp, M_, C3_, C_, 0);

    // 2) causal attention -> y (fp16)
    {
        dim3 grid(B_ * H_, T_ / 128);
        attn_mma_kernel<<<grid, 256, ATT_SMEM>>>(qkvp, yh);
    }

    // 3) out = y @ w_out + b_out  -> fp32
    gemm_f16_kernel<<<GEMM_GRID, 128, gemm_smem>>>(
        yh, wo, b_out, out, nullptr, M_, C_, C_, 1);
}

// round 15
// speedup vs baseline: 1.0222x; 1.0222x over previous
#include <cuda_runtime.h>
#include <cuda_fp16.h>
#include <math.h>
#include <stdint.h>

// Problem dims (fixed by the dataset)
#define B_   2
#define T_   2048
#define C_   1024
#define H_   16
#define HD_  64
#define C3_  (3*C_)
#define M_   (B_*T_)          // 4096 rows

// ---------------- scratch (no cudaMalloc allowed) ----------------
__device__ __half g_qkv[(size_t)M_ * C3_];      // fp16 qkv
__device__ __half g_x  [(size_t)M_ * C_];       // fp16 x
__device__ __half g_y  [(size_t)M_ * C_];       // fp16 y
__device__ __half g_wqkvT[(size_t)C3_ * C_];    // [N=3C][K=C] fp16
__device__ __half g_woutT[(size_t)C_ * C_];     // [N=C][K=C] fp16
__device__ int g_ctr[2];                        // persistent-GEMM tile counters

// ---------------- helpers ----------------
__device__ __forceinline__ uint32_t smem_u32(const void* p) {
    return (uint32_t)__cvta_generic_to_shared(p);
}
__device__ __forceinline__ void cp_async16(void* s, const void* g) {
    asm volatile("cp.async.cg.shared.global [%0], [%1], 16;\n"
                 :: "r"(smem_u32(s)), "l"(g));
}
__device__ __forceinline__ void cp_commit() {
    asm volatile("cp.async.commit_group;\n" ::);
}
__device__ __forceinline__ void cp_wait0() {
    asm volatile("cp.async.wait_group 0;\n" ::);
}
__device__ __forceinline__ void cp_wait2() {
    asm volatile("cp.async.wait_group 2;\n" ::);
}
__device__ __forceinline__ void mma_f16(float* d, const uint32_t* a, const uint32_t* b) {
    asm volatile(
        "mma.sync.aligned.m16n8k16.row.col.f32.f16.f16.f32 "
        "{%0,%1,%2,%3}, {%4,%5,%6,%7}, {%8,%9}, {%0,%1,%2,%3};\n"
        : "+f"(d[0]), "+f"(d[1]), "+f"(d[2]), "+f"(d[3])
        : "r"(a[0]), "r"(a[1]), "r"(a[2]), "r"(a[3]),
          "r"(b[0]), "r"(b[1]));
}
__device__ __forceinline__ void ldsm_x4(uint32_t* r, uint32_t addr) {
    asm volatile("ldmatrix.sync.aligned.m8n8.x4.shared.b16 {%0,%1,%2,%3}, [%4];"
                 : "=r"(r[0]), "=r"(r[1]), "=r"(r[2]), "=r"(r[3])
                 : "r"(addr));
}
__device__ __forceinline__ void ldsm_x4_trans(uint32_t* r, uint32_t addr) {
    asm volatile("ldmatrix.sync.aligned.m8n8.x4.trans.shared.b16 {%0,%1,%2,%3}, [%4];"
                 : "=r"(r[0]), "=r"(r[1]), "=r"(r[2]), "=r"(r[3])
                 : "r"(addr));
}
// pack two floats into fp16x2 (first arg -> low half)
__device__ __forceinline__ uint32_t pack_f16x2(float lo, float hi) {
    uint32_t r;
    asm("cvt.rn.f16x2.f32 %0, %1, %2;" : "=r"(r) : "f"(hi), "f"(lo));
    return r;
}

// ---------------- fused prep kernel (one launch) ----------------
#define PREP_GRID (256 + 3072 + 1024)

__global__ __launch_bounds__(256) void prep_kernel(
    const float* __restrict__ x, __half* __restrict__ xh,
    const float* __restrict__ wqkv, __half* __restrict__ wq,
    const float* __restrict__ wout, __half* __restrict__ wo)
{
    const int bid = blockIdx.x;
    const int t   = threadIdx.x;
    if (bid == 0 && t == 0) { g_ctr[0] = 0; g_ctr[1] = 0; }

    if (bid < 256) {
        const int n = M_ * C_;
        for (int i = bid * 256 + t; i < n; i += 256 * 256)
            xh[i] = __float2half_rn(x[i]);
        return;
    }

    __shared__ float ts[32][33];
    const int tx = t & 31;
    const int ty = t >> 5;
    const int K  = C_;

    const float* src; __half* dst; int N, tileid, ncols;
    if (bid < 256 + 3072) {
        tileid = bid - 256;  src = wqkv; dst = wq; N = C3_; ncols = 96;
    } else {
        tileid = bid - 3328; src = wout; dst = wo; N = C_;  ncols = 32;
    }
    const int n0 = (tileid % ncols) * 32;
    const int k0 = (tileid / ncols) * 32;
#pragma unroll
    for (int i = 0; i < 4; i++) {
        int k = k0 + ty + i * 8;
        ts[ty + i * 8][tx] = src[(size_t)k * N + n0 + tx];
    }
    __syncthreads();
#pragma unroll
    for (int i = 0; i < 4; i++) {
        int n = n0 + ty + i * 8;
        dst[(size_t)n * K + k0 + tx] = __float2half_rn(ts[tx][ty + i * 8]);
    }
}

// shared GEMM geometry
#define GBM 128
#define GBN 128
#define GBK 32
#define TSTRIDE 20                     // uint32 words per SMEM tile row (80 B)
#define TILE_WORDS (128 * TSTRIDE)     // 2560 words = 10 KB per operand tile
#define NSTAGE 4
#define GEMM_GRID 304                  // 2 CTAs x 152 SMs

// ================= fp16 persistent GEMM (4-stage pipeline) =================
// D = A[M,K] @ B^T + bias; A fp16 [M][K], B fp16 [N][K], fp32 accumulate.
// Output: fp16 (Ch != nullptr) or fp32 (Cout).
// 128 threads = 4 warps (2x2), warp tile 64x64. SMEM 80 KB/CTA (4 stages).
// Pipeline: wait_group 2 keeps 2 chunks of load slack; ONE barrier per kt.
__global__ __launch_bounds__(128, 2) void gemm_f16_kernel(
    const __half* __restrict__ A, const __half* __restrict__ Bw,
    const float* __restrict__ bias,
    float* __restrict__ Cout, __half* __restrict__ Ch,
    int M, int N, int K, int ctr_slot)
{
    extern __shared__ uint32_t sm[];
    __shared__ int s_next;
    uint32_t* tiles[NSTAGE][2];   // 0=A 1=B
#pragma unroll
    for (int s = 0; s < NSTAGE; s++)
#pragma unroll
        for (int t = 0; t < 2; t++)
            tiles[s][t] = sm + (s * 2 + t) * TILE_WORDS;

    const int tid  = threadIdx.x;
    const int wid  = tid >> 5;
    const int lane = tid & 31;
    const int g    = lane >> 2;
    const int q    = lane & 3;
    const int wm   = (wid & 1) * 64;
    const int wn   = (wid >> 1) * 64;

    const int grp = lane >> 3;
    const int rl  = lane & 7;
    uint32_t aRel[4];
#pragma unroll
    for (int mi = 0; mi < 4; mi++)
        aRel[mi] = (uint32_t)((wm + mi * 16 + (grp & 1) * 8 + rl) * 80
                              + (grp >> 1) * 16);
    uint32_t bRel[4];
#pragma unroll
    for (int ni2 = 0; ni2 < 4; ni2++)
        bRel[ni2] = (uint32_t)((wn + ni2 * 16 + (grp >> 1) * 8 + rl) * 80
                               + (grp & 1) * 16);

    const int ncol    = N / GBN;
    const int n_tiles = (M / GBM) * ncol;
    int ti = blockIdx.x;

    while (ti < n_tiles) {
        const int row0 = (ti / ncol) * GBM;
        const int col0 = (ti % ncol) * GBN;

        float acc[4][8][4];
#pragma unroll
        for (int mi = 0; mi < 4; mi++)
#pragma unroll
            for (int ni = 0; ni < 8; ni++)
#pragma unroll
                for (int r = 0; r < 4; r++) acc[mi][ni][r] = 0.f;

        const __half* srcs[2] = {A, Bw};
        auto load_tile = [&](int kt, int buf) {
            const int k0 = kt * GBK;
#pragma unroll
            for (int t = 0; t < 2; t++) {
                const __half* base = srcs[t] +
                    (size_t)((t < 1) ? row0 : col0) * K + k0;
#pragma unroll
                for (int it = 0; it < 4; it++) {
                    int idx = tid + it * 128;       // 0..511
                    int r   = idx >> 2;
                    int f   = idx & 3;
                    cp_async16(&tiles[buf][t][r * TSTRIDE + f * 4],
                               base + (size_t)r * K + f * 8);
                }
            }
            cp_commit();
        };

        // prologue: 3 chunks in flight (K=1024 -> KT=32 >= 3 always)
        load_tile(0, 0);
        load_tile(1, 1);
        load_tile(2, 2);

        const int KT = K / GBK;   // 32
        for (int kt = 0; kt < KT; kt++) {
            cp_wait2();            // chunk kt arrived (2 still in flight)
            __syncthreads();       // all warps see chunk kt; done with kt-1

            // issue chunk kt+3 into buffer (kt+3)&3 == (kt-1)&3 (free now)
            if (kt + 3 < KT) load_tile(kt + 3, (kt + 3) & (NSTAGE - 1));
            else cp_commit();      // keep group count uniform

            const uint32_t baseA = smem_u32(tiles[kt & (NSTAGE - 1)][0]);
            const uint32_t baseB = smem_u32(tiles[kt & (NSTAGE - 1)][1]);

#pragma unroll
            for (int ks = 0; ks < 2; ks++) {
                const uint32_t ko = (uint32_t)ks * 32;
                uint32_t af[4][4], bf[8][2];
#pragma unroll
                for (int mi = 0; mi < 4; mi++)
                    ldsm_x4(af[mi], baseA + aRel[mi] + ko);
#pragma unroll
                for (int ni2 = 0; ni2 < 4; ni2++) {
                    uint32_t t4[4];
                    ldsm_x4(t4, baseB + bRel[ni2] + ko);
                    bf[2*ni2][0] = t4[0]; bf[2*ni2][1] = t4[1];
                    bf[2*ni2+1][0] = t4[2]; bf[2*ni2+1][1] = t4[3];
                }
#pragma unroll
                for (int mi = 0; mi < 4; mi++)
#pragma unroll
                    for (int ni = 0; ni < 8; ni++)
                        mma_f16(acc[mi][ni], af[mi], bf[ni]);
            }
        }
        cp_wait0();               // drain empty groups before next tile

        // ---- epilogue ----
#pragma unroll
        for (int mi = 0; mi < 4; mi++) {
#pragma unroll
            for (int ni = 0; ni < 8; ni++) {
                int r = row0 + wm + mi * 16 + g;
                int c = col0 + wn + ni * 8 + 2 * q;
                float b0 = bias[c], b1 = bias[c + 1];
                float v00 = acc[mi][ni][0] + b0, v01 = acc[mi][ni][1] + b1;
                float v10 = acc[mi][ni][2] + b0, v11 = acc[mi][ni][3] + b1;
                if (Ch) {
                    *(uint32_t*)(Ch + (size_t)r * N + c)       = pack_f16x2(v00, v01);
                    *(uint32_t*)(Ch + (size_t)(r + 8) * N + c) = pack_f16x2(v10, v11);
                } else {
                    *(float2*)(Cout + (size_t)r * N + c)       = make_float2(v00, v01);
                    *(float2*)(Cout + (size_t)(r + 8) * N + c) = make_float2(v10, v11);
                }
            }
        }

        if (tid == 0) s_next = (int)gridDim.x + atomicAdd(&g_ctr[ctr_slot], 1);
        __syncthreads();
        ti = s_next;
        __syncthreads();
    }
}

// ================= MMA flash attention (fp16, fp32 softmax) ========
// (unchanged from R13 — controlled experiment)
#define ATT_SMEM (9216 * 4)

__global__ __launch_bounds__(256, 2) void attn_mma_kernel(
    const __half* __restrict__ qkv, __half* __restrict__ y)
{
    extern __shared__ uint32_t smd[];
    uint32_t* smB[2] = {smd, smd + 4608};

    const int tid  = threadIdx.x;
    const int w    = tid >> 5;
    const int lane = tid & 31;
    const int g    = lane >> 2;
    const int q    = lane & 3;
    const int grp  = lane >> 3;
    const int rl   = lane & 7;
    const int bh   = blockIdx.x;
    const int b    = bh >> 4;
    const int h    = bh & 15;
    const int qt   = (gridDim.y - 1) - blockIdx.y;   // heavy blocks first
    const int qb   = qt * 128;

    // ---- stage Q, extract fragments ----
#pragma unroll
    for (int it = 0; it < 4; it++) {
        int idx = tid + it * 256;            // 0..1023
        int row = idx >> 3;
        int ch  = idx & 7;
        const __half* src = qkv
            + (size_t)(b * T_ + qb + row) * C3_ + h * HD_ + ch * 8;
        cp_async16(&smd[row * 36 + ch * 4], src);
    }
    cp_commit();
    cp_wait0();
    __syncthreads();

    uint32_t qf[4][4];
    {
        uint32_t qa = smem_u32(&smd[0])
            + (uint32_t)((w * 16 + (grp & 1) * 8 + rl) * 144 + (grp >> 1) * 16);
#pragma unroll
        for (int ks = 0; ks < 4; ks++)
            ldsm_x4(qf[ks], qa + ks * 32);
    }
    __syncthreads();   // SMEM free for K/V

    const __half* kv_src[2] = {qkv + C_, qkv + 2 * C_};
    auto load_tile = [&](int kt, int bufi) {
        const int k0 = kt * 64;
#pragma unroll
        for (int it = 0; it < 4; it++) {
            int idx = tid + it * 256;        // 0..1023
            int arr = idx >> 9;              // 0=K,1=V
            int rem = idx & 511;
            int row = rem >> 3;
            int ch  = rem & 7;
            const __half* src = kv_src[arr]
                + (size_t)(b * T_ + k0 + row) * C3_ + h * HD_ + ch * 8;
            cp_async16(&smB[bufi][arr * 2304 + row * 36 + ch * 4], src);
        }
        cp_commit();
    };

    float o[8][4];
#pragma unroll
    for (int nj = 0; nj < 8; nj++)
#pragma unroll
        for (int c = 0; c < 4; c++) o[nj][c] = 0.f;
    float m0 = -INFINITY, m1 = -INFINITY;
    float l0 = 0.f, l1 = 0.f;

    const int qrow0 = qb + w * 16 + g;
    const int qrow1 = qrow0 + 8;
    const int qmax_w = qb + w * 16 + 15;
    const int kt_max = (qb + 127) >> 6;

    load_tile(0, 0);
    cp_wait0();
    __syncthreads();

    for (int kt = 0; kt <= kt_max; kt++) {
        const int bufi = kt & 1;
        const int k0 = kt * 64;
        if (kt + 1 <= kt_max) load_tile(kt + 1, bufi ^ 1);

        if (k0 <= qmax_w) {
            const uint32_t sb = smem_u32(&smB[bufi][0]);

            // ---- S = Q K^T ----
            float s[8][4];
#pragma unroll
            for (int ni2 = 0; ni2 < 4; ni2++) {
#pragma unroll
                for (int c = 0; c < 4; c++) {
                    s[2*ni2][c] = 0.f; s[2*ni2+1][c] = 0.f;
                }
                const uint32_t ka = sb
                    + (uint32_t)((ni2 * 16 + (grp >> 1) * 8 + rl) * 144
                                 + (grp & 1) * 16);
#pragma unroll
                for (int ks = 0; ks < 4; ks++) {
                    uint32_t k4[4];
                    ldsm_x4(k4, ka + ks * 32);
                    mma_f16(s[2*ni2],   qf[ks], k4);
                    mma_f16(s[2*ni2+1], qf[ks], k4 + 2);
                }
            }
#pragma unroll
            for (int ni = 0; ni < 8; ni++)
#pragma unroll
                for (int c = 0; c < 4; c++) s[ni][c] *= 0.125f;

            // ---- causal mask ----
            if (k0 + 63 > qb + w * 16) {
#pragma unroll
                for (int ni = 0; ni < 8; ni++) {
                    int key = k0 + 8 * ni + 2 * q;
                    s[ni][0] = (key     <= qrow0) ? s[ni][0] : -INFINITY;
                    s[ni][1] = (key + 1 <= qrow0) ? s[ni][1] : -INFINITY;
                    s[ni][2] = (key     <= qrow1) ? s[ni][2] : -INFINITY;
                    s[ni][3] = (key + 1 <= qrow1) ? s[ni][3] : -INFINITY;
                }
            }

            // ---- online softmax ----
            float mx0 = s[0][0], mx1 = s[0][2];
#pragma unroll
            for (int ni = 0; ni < 8; ni++) {
                mx0 = fmaxf(mx0, fmaxf(s[ni][0], s[ni][1]));
                mx1 = fmaxf(mx1, fmaxf(s[ni][2], s[ni][3]));
            }
            mx0 = fmaxf(mx0, __shfl_xor_sync(0xffffffff, mx0, 1));
            mx0 = fmaxf(mx0, __shfl_xor_sync(0xffffffff, mx0, 2));
            mx1 = fmaxf(mx1, __shfl_xor_sync(0xffffffff, mx1, 1));
            mx1 = fmaxf(mx1, __shfl_xor_sync(0xffffffff, mx1, 2));

            float mn0 = fmaxf(m0, mx0), mn1 = fmaxf(m1, mx1);
            float al0 = __expf(m0 - mn0), al1 = __expf(m1 - mn1);
            m0 = mn0; m1 = mn1;
            l0 *= al0; l1 *= al1;
#pragma unroll
            for (int nj = 0; nj < 8; nj++) {
                o[nj][0] *= al0; o[nj][1] *= al0;
                o[nj][2] *= al1; o[nj][3] *= al1;
            }

            // ---- per k16 step: pack P, O += P V ----
#pragma unroll
            for (int ks = 0; ks < 4; ks++) {
                uint32_t af[4];
#pragma unroll
                for (int half = 0; half < 2; half++) {
                    const int ni = 2 * ks + half;
                    float p0 = __expf(s[ni][0] - mn0);
                    float p1 = __expf(s[ni][1] - mn0);
                    float p2 = __expf(s[ni][2] - mn1);
                    float p3 = __expf(s[ni][3] - mn1);
                    l0 += p0 + p1;
                    l1 += p2 + p3;
                    af[2*half]     = pack_f16x2(p0, p1);
                    af[2*half + 1] = pack_f16x2(p2, p3);
                }
                const uint32_t va = sb + 2304 * 4
                    + (uint32_t)((ks * 16 + (grp & 1) * 8 + rl) * 144
                                 + (grp >> 1) * 16);
#pragma unroll
                for (int nj2 = 0; nj2 < 4; nj2++) {
                    uint32_t v4[4];
                    ldsm_x4_trans(v4, va + nj2 * 32);
                    mma_f16(o[2*nj2],   af, v4);
                    mma_f16(o[2*nj2+1], af, v4 + 2);
                }
            }
        }

        cp_wait0();
        __syncthreads();
    }

    // ---- epilogue ----
    l0 += __shfl_xor_sync(0xffffffff, l0, 1);
    l0 += __shfl_xor_sync(0xffffffff, l0, 2);
    l1 += __shfl_xor_sync(0xffffffff, l1, 1);
    l1 += __shfl_xor_sync(0xffffffff, l1, 2);
    const float inv0 = 1.f / l0;
    const float inv1 = 1.f / l1;

    __half* y0 = y + (size_t)(b * T_ + qrow0) * C_ + h * HD_;
    __half* y1 = y + (size_t)(b * T_ + qrow1) * C_ + h * HD_;
#pragma unroll
    for (int nj = 0; nj < 8; nj++) {
        int c = 8 * nj + 2 * q;
        *(uint32_t*)(y0 + c) = pack_f16x2(o[nj][0] * inv0, o[nj][1] * inv0);
        *(uint32_t*)(y1 + c) = pack_f16x2(o[nj][2] * inv1, o[nj][3] * inv1);
    }
}

// ---------------- launch ----------------
extern "C" void kernel_launch(void* const* d_in, const int* in_sizes, int n_in,
                              void* d_out, int out_size)
{
    const float* x     = (const float*)d_in[0];
    const float* w_qkv = (const float*)d_in[1];
    const float* b_qkv = (const float*)d_in[2];
    const float* w_out = (const float*)d_in[3];
    const float* b_out = (const float*)d_in[4];
    float* out = (float*)d_out;

    __half *qkvp, *xh, *yh, *wq, *wo;
    cudaGetSymbolAddress((void**)&qkvp, g_qkv);
    cudaGetSymbolAddress((void**)&xh, g_x);
    cudaGetSymbolAddress((void**)&yh, g_y);
    cudaGetSymbolAddress((void**)&wq, g_wqkvT);
    cudaGetSymbolAddress((void**)&wo, g_woutT);

    static bool attr_set = false;
    if (!attr_set) {
        cudaFuncSetAttribute(gemm_f16_kernel,
                             cudaFuncAttributeMaxDynamicSharedMemorySize,
                             NSTAGE * 2 * TILE_WORDS * 4);
        cudaFuncSetAttribute(attn_mma_kernel,
                             cudaFuncAttributeMaxDynamicSharedMemorySize,
                             ATT_SMEM);
        attr_set = true;
    }
    const int gemm_smem = NSTAGE * 2 * TILE_WORDS * 4;   // 81920 B

    // 0) fused prep: convert x, transpose+convert both weights
    prep_kernel<<<PREP_GRID, 256>>>(x, xh, w_qkv, wq, w_out, wo);

    // 1) qkv = x @ w_qkv + b_qkv  -> fp16
    gemm_f16_kernel<<<GEMM_GRID, 128, gemm_smem>>>(
        xh, wq, b_qkv, nullptr, qkvp, M_, C3_, C_, 0);

    // 2) causal attention -> y (fp16)
    {
        dim3 grid(B_ * H_, T_ / 128);
        attn_mma_kernel<<<grid, 256, ATT_SMEM>>>(qkvp, yh);
    }

    // 3) out = y @ w_out + b_out  -> fp32
    gemm_f16_kernel<<<GEMM_GRID, 128, gemm_smem>>>(
        yh, wo, b_out, out, nullptr, M_, C_, C_, 1);
}